// round 1
// baseline (speedup 1.0000x reference)
#include <cuda_runtime.h>
#include <cuda_bf16.h>
#include <math.h>

// Problem dims (fixed by the reference)
#define BATCH 256
#define NPIX  196
#define CDIM  2048
#define ADIM  512
#define LDIM  512
#define MTOT  (BATCH * NPIX)   // 50176 = 392 * 128

// GEMM tiling
#define BM 128
#define BN 128
#define BK 16
#define NBLK (ADIM / BN)       // 4

// Scratch (device globals — no allocation allowed)
__device__ float g_att2[BATCH * ADIM];        // (B, A)
__device__ float g_att_part[NBLK * MTOT];     // per-N-block partial scores
__device__ float g_alpha[MTOT];               // softmax weights

// ---------------------------------------------------------------------------
// K1: att2[b][a] = lstm[b] . Wl[a] + bl[a]
// 512 threads per block, 8 batches per block (32 blocks).
// ---------------------------------------------------------------------------
__global__ void att2_kernel(const float* __restrict__ lstm,
                            const float* __restrict__ Wl,
                            const float* __restrict__ bl,
                            float* __restrict__ att2) {
    __shared__ float h[8][LDIM];
    const int b0 = blockIdx.x * 8;
    const int a = threadIdx.x;   // 0..511

    #pragma unroll
    for (int i = 0; i < 8; i++)
        h[i][a] = lstm[(b0 + i) * LDIM + a];
    __syncthreads();

    const float4* w4 = reinterpret_cast<const float4*>(Wl + (size_t)a * LDIM);
    float acc[8] = {0.f, 0.f, 0.f, 0.f, 0.f, 0.f, 0.f, 0.f};
    #pragma unroll 4
    for (int l4 = 0; l4 < LDIM / 4; l4++) {
        float4 wv = w4[l4];
        int l = l4 * 4;
        #pragma unroll
        for (int i = 0; i < 8; i++) {
            acc[i] += h[i][l + 0] * wv.x;
            acc[i] += h[i][l + 1] * wv.y;
            acc[i] += h[i][l + 2] * wv.z;
            acc[i] += h[i][l + 3] * wv.w;
        }
    }
    const float bv = bl[a];
    #pragma unroll
    for (int i = 0; i < 8; i++)
        att2[(b0 + i) * ADIM + a] = acc[i] + bv;
}

// ---------------------------------------------------------------------------
// K2: fused score GEMM.
//   C[m][n] = conv[m] . Wc[n]   (m in 0..50175, n in 0..511)
//   partial[bn][m] = sum_{n in bn-block} relu(C[m][n] + bc[n] + att2[b][n]) * Wf[n]
// 128x128x16 tile, 256 threads, 8x8 per thread, fp32.
// ---------------------------------------------------------------------------
__global__ __launch_bounds__(256, 2)
void score_gemm_kernel(const float* __restrict__ A,    // conv_out, M x K
                       const float* __restrict__ Wc,   // N x K
                       const float* __restrict__ bc,
                       const float* __restrict__ Wf,   // (1, 512)
                       const float* __restrict__ att2, // B x 512
                       float* __restrict__ att_part)   // NBLK x M
{
    __shared__ float As[BK][BM + 4];
    __shared__ float Bs[BK][BN + 4];

    const int bm = blockIdx.x;             // 0..391
    const int bn = blockIdx.y;             // 0..3
    const int tid = threadIdx.x;           // 0..255
    const int tx = tid & 15;
    const int ty = tid >> 4;

    float acc[8][8];
    #pragma unroll
    for (int i = 0; i < 8; i++)
        #pragma unroll
        for (int j = 0; j < 8; j++) acc[i][j] = 0.f;

    const float* Ab = A  + (size_t)bm * BM * CDIM;
    const float* Bb = Wc + (size_t)bn * BN * CDIM;

    const int l_row  = tid >> 2;   // 0..63
    const int l_col4 = tid & 3;    // 0..3  (float4 index within 16-wide row)

    for (int k0 = 0; k0 < CDIM; k0 += BK) {
        #pragma unroll
        for (int i = 0; i < 2; i++) {
            const int r = l_row + i * 64;
            float4 v = *reinterpret_cast<const float4*>(Ab + (size_t)r * CDIM + k0 + l_col4 * 4);
            As[l_col4 * 4 + 0][r] = v.x;
            As[l_col4 * 4 + 1][r] = v.y;
            As[l_col4 * 4 + 2][r] = v.z;
            As[l_col4 * 4 + 3][r] = v.w;
            float4 w = *reinterpret_cast<const float4*>(Bb + (size_t)r * CDIM + k0 + l_col4 * 4);
            Bs[l_col4 * 4 + 0][r] = w.x;
            Bs[l_col4 * 4 + 1][r] = w.y;
            Bs[l_col4 * 4 + 2][r] = w.z;
            Bs[l_col4 * 4 + 3][r] = w.w;
        }
        __syncthreads();

        #pragma unroll
        for (int kk = 0; kk < BK; kk++) {
            float4 a0 = *reinterpret_cast<const float4*>(&As[kk][ty * 8]);
            float4 a1 = *reinterpret_cast<const float4*>(&As[kk][ty * 8 + 4]);
            float4 b0 = *reinterpret_cast<const float4*>(&Bs[kk][tx * 8]);
            float4 b1 = *reinterpret_cast<const float4*>(&Bs[kk][tx * 8 + 4]);
            float af[8] = {a0.x, a0.y, a0.z, a0.w, a1.x, a1.y, a1.z, a1.w};
            float bfr[8] = {b0.x, b0.y, b0.z, b0.w, b1.x, b1.y, b1.z, b1.w};
            #pragma unroll
            for (int i = 0; i < 8; i++)
                #pragma unroll
                for (int j = 0; j < 8; j++)
                    acc[i][j] += af[i] * bfr[j];
        }
        __syncthreads();
    }

    // Epilogue: relu(acc + bc + att2) . Wf, reduced per row (deterministic).
    float wf[8], bcv[8];
    #pragma unroll
    for (int j = 0; j < 8; j++) {
        const int n = bn * BN + tx * 8 + j;
        wf[j]  = Wf[n];
        bcv[j] = bc[n];
    }

    __shared__ float red[BM][17];   // [row][tx], padded
    #pragma unroll
    for (int i = 0; i < 8; i++) {
        const int m = bm * BM + ty * 8 + i;
        const int b = m / NPIX;
        const float* a2 = att2 + (size_t)b * ADIM + bn * BN + tx * 8;
        float s = 0.f;
        #pragma unroll
        for (int j = 0; j < 8; j++) {
            float v = acc[i][j] + bcv[j] + a2[j];
            v = fmaxf(v, 0.f) * wf[j];
            s += v;
        }
        red[ty * 8 + i][tx] = s;
    }
    __syncthreads();

    if (tid < BM) {
        float s = 0.f;
        #pragma unroll
        for (int t = 0; t < 16; t++) s += red[tid][t];
        att_part[(size_t)bn * MTOT + bm * BM + tid] = s;
    }
}

// ---------------------------------------------------------------------------
// K3: softmax over P=196 per batch row.
// ---------------------------------------------------------------------------
__global__ void softmax_kernel(const float* __restrict__ att_part,
                               const float* __restrict__ bf,
                               float* __restrict__ alpha) {
    __shared__ float sv[256];
    const int b = blockIdx.x;
    const int tid = threadIdx.x;

    float val = 0.f;
    float v = -INFINITY;
    if (tid < NPIX) {
        const int m = b * NPIX + tid;
        val = bf[0]
            + att_part[0 * MTOT + m]
            + att_part[1 * MTOT + m]
            + att_part[2 * MTOT + m]
            + att_part[3 * MTOT + m];
        v = val;
    }
    sv[tid] = v;
    __syncthreads();
    #pragma unroll
    for (int s = 128; s > 0; s >>= 1) {
        if (tid < s) sv[tid] = fmaxf(sv[tid], sv[tid + s]);
        __syncthreads();
    }
    const float mx = sv[0];
    __syncthreads();

    const float e = (tid < NPIX) ? expf(val - mx) : 0.f;
    sv[tid] = e;
    __syncthreads();
    #pragma unroll
    for (int s = 128; s > 0; s >>= 1) {
        if (tid < s) sv[tid] = sv[tid] + sv[tid + s];
        __syncthreads();
    }
    const float sum = sv[0];
    if (tid < NPIX) alpha[b * NPIX + tid] = e / sum;
}

// ---------------------------------------------------------------------------
// K4: out[b][c] = sum_p conv[b][p][c] * alpha[b][p]   (memory bound)
// ---------------------------------------------------------------------------
__global__ void pool_kernel(const float* __restrict__ conv,
                            const float* __restrict__ alpha,
                            float* __restrict__ out) {
    __shared__ float al[NPIX];
    const int b = blockIdx.y;
    const int c = blockIdx.x * 256 + threadIdx.x;
    if (threadIdx.x < NPIX) al[threadIdx.x] = alpha[b * NPIX + threadIdx.x];
    __syncthreads();

    const float* cp = conv + (size_t)b * NPIX * CDIM + c;
    float acc = 0.f;
    #pragma unroll 4
    for (int p = 0; p < NPIX; p++)
        acc += cp[(size_t)p * CDIM] * al[p];
    out[(size_t)b * CDIM + c] = acc;
}

// ---------------------------------------------------------------------------
extern "C" void kernel_launch(void* const* d_in, const int* in_sizes, int n_in,
                              void* d_out, int out_size) {
    const float* conv = (const float*)d_in[0];
    const float* lstm = (const float*)d_in[1];
    const float* Wc   = (const float*)d_in[2];
    const float* bc   = (const float*)d_in[3];
    const float* Wl   = (const float*)d_in[4];
    const float* bl   = (const float*)d_in[5];
    const float* Wf   = (const float*)d_in[6];
    const float* bf   = (const float*)d_in[7];
    float* out = (float*)d_out;

    float* att2;     cudaGetSymbolAddress((void**)&att2, g_att2);
    float* att_part; cudaGetSymbolAddress((void**)&att_part, g_att_part);
    float* alpha;    cudaGetSymbolAddress((void**)&alpha, g_alpha);

    att2_kernel<<<BATCH / 8, LDIM>>>(lstm, Wl, bl, att2);

    dim3 gg(MTOT / BM, NBLK);
    score_gemm_kernel<<<gg, 256>>>(conv, Wc, bc, Wf, att2, att_part);

    softmax_kernel<<<BATCH, 256>>>(att_part, bf, alpha);

    pool_kernel<<<dim3(CDIM / 256, BATCH), 256>>>(conv, alpha, out);
}

// round 2
// speedup vs baseline: 1.0002x; 1.0002x over previous
#include <cuda_runtime.h>
#include <cuda_bf16.h>
#include <math.h>

// Problem dims (fixed by the reference)
#define BATCH 256
#define NPIX  196
#define CDIM  2048
#define ADIM  512
#define LDIM  512
#define MTOT  (BATCH * NPIX)   // 50176 = 392 * 128

// GEMM tiling
#define BM 128
#define BN 128
#define BK 16
#define NBLK (ADIM / BN)       // 4

// Scratch (device globals — no allocation allowed)
__device__ float g_att2[BATCH * ADIM];        // (B, A)
__device__ float g_att_part[NBLK * MTOT];     // per-N-block partial scores
__device__ float g_alpha[MTOT];               // softmax weights

// ---------------------------------------------------------------------------
// K1: att2[b][a] = lstm[b] . Wl[a] + bl[a]
// 512 threads per block, 8 batches per block (32 blocks).
// ---------------------------------------------------------------------------
__global__ void att2_kernel(const float* __restrict__ lstm,
                            const float* __restrict__ Wl,
                            const float* __restrict__ bl,
                            float* __restrict__ att2) {
    __shared__ float h[8][LDIM];
    const int b0 = blockIdx.x * 8;
    const int a = threadIdx.x;   // 0..511

    #pragma unroll
    for (int i = 0; i < 8; i++)
        h[i][a] = lstm[(b0 + i) * LDIM + a];
    __syncthreads();

    const float4* w4 = reinterpret_cast<const float4*>(Wl + (size_t)a * LDIM);
    float acc[8] = {0.f, 0.f, 0.f, 0.f, 0.f, 0.f, 0.f, 0.f};
    #pragma unroll 4
    for (int l4 = 0; l4 < LDIM / 4; l4++) {
        float4 wv = w4[l4];
        int l = l4 * 4;
        #pragma unroll
        for (int i = 0; i < 8; i++) {
            acc[i] += h[i][l + 0] * wv.x;
            acc[i] += h[i][l + 1] * wv.y;
            acc[i] += h[i][l + 2] * wv.z;
            acc[i] += h[i][l + 3] * wv.w;
        }
    }
    const float bv = bl[a];
    #pragma unroll
    for (int i = 0; i < 8; i++)
        att2[(b0 + i) * ADIM + a] = acc[i] + bv;
}

// ---------------------------------------------------------------------------
// K2: fused score GEMM.
//   C[m][n] = conv[m] . Wc[n]   (m in 0..50175, n in 0..511)
//   partial[bn][m] = sum_{n in bn-block} relu(C[m][n] + bc[n] + att2[b][n]) * Wf[n]
// 128x128x16 tile, 256 threads, 8x8 per thread, fp32.
// ---------------------------------------------------------------------------
__global__ __launch_bounds__(256, 2)
void score_gemm_kernel(const float* __restrict__ A,    // conv_out, M x K
                       const float* __restrict__ Wc,   // N x K
                       const float* __restrict__ bc,
                       const float* __restrict__ Wf,   // (1, 512)
                       const float* __restrict__ att2, // B x 512
                       float* __restrict__ att_part)   // NBLK x M
{
    __shared__ float As[BK][BM + 4];
    __shared__ float Bs[BK][BN + 4];

    const int bm = blockIdx.x;             // 0..391
    const int bn = blockIdx.y;             // 0..3
    const int tid = threadIdx.x;           // 0..255
    const int tx = tid & 15;
    const int ty = tid >> 4;

    float acc[8][8];
    #pragma unroll
    for (int i = 0; i < 8; i++)
        #pragma unroll
        for (int j = 0; j < 8; j++) acc[i][j] = 0.f;

    const float* Ab = A  + (size_t)bm * BM * CDIM;
    const float* Bb = Wc + (size_t)bn * BN * CDIM;

    const int l_row  = tid >> 2;   // 0..63
    const int l_col4 = tid & 3;    // 0..3  (float4 index within 16-wide row)

    for (int k0 = 0; k0 < CDIM; k0 += BK) {
        #pragma unroll
        for (int i = 0; i < 2; i++) {
            const int r = l_row + i * 64;
            float4 v = *reinterpret_cast<const float4*>(Ab + (size_t)r * CDIM + k0 + l_col4 * 4);
            As[l_col4 * 4 + 0][r] = v.x;
            As[l_col4 * 4 + 1][r] = v.y;
            As[l_col4 * 4 + 2][r] = v.z;
            As[l_col4 * 4 + 3][r] = v.w;
            float4 w = *reinterpret_cast<const float4*>(Bb + (size_t)r * CDIM + k0 + l_col4 * 4);
            Bs[l_col4 * 4 + 0][r] = w.x;
            Bs[l_col4 * 4 + 1][r] = w.y;
            Bs[l_col4 * 4 + 2][r] = w.z;
            Bs[l_col4 * 4 + 3][r] = w.w;
        }
        __syncthreads();

        #pragma unroll
        for (int kk = 0; kk < BK; kk++) {
            float4 a0 = *reinterpret_cast<const float4*>(&As[kk][ty * 8]);
            float4 a1 = *reinterpret_cast<const float4*>(&As[kk][ty * 8 + 4]);
            float4 b0 = *reinterpret_cast<const float4*>(&Bs[kk][tx * 8]);
            float4 b1 = *reinterpret_cast<const float4*>(&Bs[kk][tx * 8 + 4]);
            float af[8] = {a0.x, a0.y, a0.z, a0.w, a1.x, a1.y, a1.z, a1.w};
            float bfr[8] = {b0.x, b0.y, b0.z, b0.w, b1.x, b1.y, b1.z, b1.w};
            #pragma unroll
            for (int i = 0; i < 8; i++)
                #pragma unroll
                for (int j = 0; j < 8; j++)
                    acc[i][j] += af[i] * bfr[j];
        }
        __syncthreads();
    }

    // Epilogue: relu(acc + bc + att2) . Wf, reduced per row (deterministic).
    float wf[8], bcv[8];
    #pragma unroll
    for (int j = 0; j < 8; j++) {
        const int n = bn * BN + tx * 8 + j;
        wf[j]  = Wf[n];
        bcv[j] = bc[n];
    }

    __shared__ float red[BM][17];   // [row][tx], padded
    #pragma unroll
    for (int i = 0; i < 8; i++) {
        const int m = bm * BM + ty * 8 + i;
        const int b = m / NPIX;
        const float* a2 = att2 + (size_t)b * ADIM + bn * BN + tx * 8;
        float s = 0.f;
        #pragma unroll
        for (int j = 0; j < 8; j++) {
            float v = acc[i][j] + bcv[j] + a2[j];
            v = fmaxf(v, 0.f) * wf[j];
            s += v;
        }
        red[ty * 8 + i][tx] = s;
    }
    __syncthreads();

    if (tid < BM) {
        float s = 0.f;
        #pragma unroll
        for (int t = 0; t < 16; t++) s += red[tid][t];
        att_part[(size_t)bn * MTOT + bm * BM + tid] = s;
    }
}

// ---------------------------------------------------------------------------
// K3: softmax over P=196 per batch row.
// ---------------------------------------------------------------------------
__global__ void softmax_kernel(const float* __restrict__ att_part,
                               const float* __restrict__ bf,
                               float* __restrict__ alpha) {
    __shared__ float sv[256];
    const int b = blockIdx.x;
    const int tid = threadIdx.x;

    float val = 0.f;
    float v = -INFINITY;
    if (tid < NPIX) {
        const int m = b * NPIX + tid;
        val = bf[0]
            + att_part[0 * MTOT + m]
            + att_part[1 * MTOT + m]
            + att_part[2 * MTOT + m]
            + att_part[3 * MTOT + m];
        v = val;
    }
    sv[tid] = v;
    __syncthreads();
    #pragma unroll
    for (int s = 128; s > 0; s >>= 1) {
        if (tid < s) sv[tid] = fmaxf(sv[tid], sv[tid + s]);
        __syncthreads();
    }
    const float mx = sv[0];
    __syncthreads();

    const float e = (tid < NPIX) ? expf(val - mx) : 0.f;
    sv[tid] = e;
    __syncthreads();
    #pragma unroll
    for (int s = 128; s > 0; s >>= 1) {
        if (tid < s) sv[tid] = sv[tid] + sv[tid + s];
        __syncthreads();
    }
    const float sum = sv[0];
    if (tid < NPIX) alpha[b * NPIX + tid] = e / sum;
}

// ---------------------------------------------------------------------------
// K4: out[b][c] = sum_p conv[b][p][c] * alpha[b][p]   (memory bound)
// ---------------------------------------------------------------------------
__global__ void pool_kernel(const float* __restrict__ conv,
                            const float* __restrict__ alpha,
                            float* __restrict__ out) {
    __shared__ float al[NPIX];
    const int b = blockIdx.y;
    const int c = blockIdx.x * 256 + threadIdx.x;
    if (threadIdx.x < NPIX) al[threadIdx.x] = alpha[b * NPIX + threadIdx.x];
    __syncthreads();

    const float* cp = conv + (size_t)b * NPIX * CDIM + c;
    float acc = 0.f;
    #pragma unroll 4
    for (int p = 0; p < NPIX; p++)
        acc += cp[(size_t)p * CDIM] * al[p];
    out[(size_t)b * CDIM + c] = acc;
}

// ---------------------------------------------------------------------------
extern "C" void kernel_launch(void* const* d_in, const int* in_sizes, int n_in,
                              void* d_out, int out_size) {
    const float* conv = (const float*)d_in[0];
    const float* lstm = (const float*)d_in[1];
    const float* Wc   = (const float*)d_in[2];
    const float* bc   = (const float*)d_in[3];
    const float* Wl   = (const float*)d_in[4];
    const float* bl   = (const float*)d_in[5];
    const float* Wf   = (const float*)d_in[6];
    const float* bf   = (const float*)d_in[7];
    float* out = (float*)d_out;

    float* att2;     cudaGetSymbolAddress((void**)&att2, g_att2);
    float* att_part; cudaGetSymbolAddress((void**)&att_part, g_att_part);
    float* alpha;    cudaGetSymbolAddress((void**)&alpha, g_alpha);

    att2_kernel<<<BATCH / 8, LDIM>>>(lstm, Wl, bl, att2);

    dim3 gg(MTOT / BM, NBLK);
    score_gemm_kernel<<<gg, 256>>>(conv, Wc, bc, Wf, att2, att_part);

    softmax_kernel<<<BATCH, 256>>>(att_part, bf, alpha);

    pool_kernel<<<dim3(CDIM / 256, BATCH), 256>>>(conv, alpha, out);
}